// round 12
// baseline (speedup 1.0000x reference)
#include <cuda_runtime.h>
#include <math.h>

// ---------------- scratch (static device globals; no allocation) ----------------
__device__ float g_part1[512 * 800];           // gemm1 partials: [chunk][r*100+j]
__device__ float g_p1b[800 * 64];              // stage-A reduced: [o][cgroup]
__device__ float g_bn[32];                     // boxNew (8,4)
__device__ float g_feat[8 * 24576];            // pooled features (B, 3*64*128)
__device__ float g_part2[7 * 128 * 8 * 128];   // head partials: [k][ch][r][h]

// ---------------- stage 1: xf(8x65536) @ wr2_w1(65536x100), split-K ----------------
__global__ void __launch_bounds__(128) k_gemm1_part(const float* __restrict__ x3,
                                                    const float* __restrict__ w1) {
    __shared__ __align__(16) float xs[8 * 128];
    __shared__ float red[4 * 800];
    const int bx = blockIdx.x;
    const int k0 = bx * 128;
    const int tid = threadIdx.x;

    const float4* x4 = (const float4*)x3;
    float4* xs4 = (float4*)xs;
#pragma unroll
    for (int t = 0; t < 2; t++) {
        int idx = tid + t * 128;
        int r = idx >> 5, q = idx & 31;
        xs4[idx] = x4[r * 16384 + bx * 32 + q];
    }
    __syncthreads();

    if (tid < 100) {
        const int ks = tid / 25;
        const int j4 = tid - ks * 25;
        const float4* w4 = (const float4*)w1;
        float acc[8][4] = {};
#pragma unroll
        for (int t = 0; t < 32; t++) {
            int kk = ks + 4 * t;
            float4 wv = w4[(size_t)(k0 + kk) * 25 + j4];
#pragma unroll
            for (int r = 0; r < 8; r++) {
                float f = xs[r * 128 + kk];
                acc[r][0] = fmaf(f, wv.x, acc[r][0]);
                acc[r][1] = fmaf(f, wv.y, acc[r][1]);
                acc[r][2] = fmaf(f, wv.z, acc[r][2]);
                acc[r][3] = fmaf(f, wv.w, acc[r][3]);
            }
        }
#pragma unroll
        for (int jj = 0; jj < 4; jj++)
#pragma unroll
            for (int r = 0; r < 8; r++)
                red[ks * 800 + r * 100 + j4 * 4 + jj] = acc[r][jj];
    }
    __syncthreads();
    for (int t = tid; t < 800; t += 128) {
        float s = red[t] + red[800 + t] + red[1600 + t] + red[2400 + t];
        g_part1[(size_t)bx * 800 + t] = s;
    }
}

// ---------------- stage 1b: coalesced stage-A reduce (64 blocks x 256) --------------
__global__ void __launch_bounds__(256) k_reduce_a() {
    const int cg = blockIdx.x;
    const int tid = threadIdx.x;
    float a0 = 0.f, a1 = 0.f, a2 = 0.f, a3 = 0.f;
    const float* base = g_part1 + (size_t)cg * 8 * 800;
#pragma unroll
    for (int q = 0; q < 8; q++) {
        const float* row = base + q * 800;
        a0 += row[tid];
        a1 += row[tid + 256];
        a2 += row[tid + 512];
        if (tid < 32) a3 += row[tid + 768];
    }
    g_p1b[(size_t)tid * 64 + cg] = a0;
    g_p1b[(size_t)(tid + 256) * 64 + cg] = a1;
    g_p1b[(size_t)(tid + 512) * 64 + cg] = a2;
    if (tid < 32) g_p1b[(size_t)(tid + 768) * 64 + cg] = a3;
}

// ---------------- stage 2: stage-B reduce + MLP + box transform (8 blocks) ----------
__global__ void __launch_bounds__(128) k_box(const float* __restrict__ b1,
                                             const float* __restrict__ w2,
                                             const float* __restrict__ b2,
                                             const float* __restrict__ w3,
                                             const float* __restrict__ b3) {
    __shared__ __align__(16) float w2s[10000];
    __shared__ float t1[100], t2[104], bl[4];
    const int b = blockIdx.x;
    const int tid = threadIdx.x;

    const float4* w24 = (const float4*)w2;
    float4* w2s4 = (float4*)w2s;
    for (int t = tid; t < 2500; t += 128) w2s4[t] = w24[t];

    if (tid < 100) {
        const float4* p = (const float4*)&g_p1b[(size_t)(b * 100 + tid) * 64];
        float s = 0.f;
#pragma unroll
        for (int q = 0; q < 16; q++) {
            float4 v = p[q];
            s += v.x + v.y + v.z + v.w;
        }
        t1[tid] = s + b1[tid];
    }
    __syncthreads();

    if (tid < 100) {
        float acc = b2[tid];
#pragma unroll 4
        for (int i = 0; i < 100; i++) acc = fmaf(t1[i], w2s[i * 100 + tid], acc);
        t2[tid] = acc;
    }
    __syncthreads();
    if (tid < 4) {
        float acc = b3[tid];
#pragma unroll 4
        for (int i = 0; i < 100; i++) acc = fmaf(t2[i], w3[i * 4 + tid], acc);
        bl[tid] = acc;
    }
    __syncthreads();
    if (tid < 4) {
        float v;
        if (tid == 0)      v = bl[0] - 0.5f * bl[2];
        else if (tid == 1) v = bl[1] - 0.5f * bl[3];
        else if (tid == 2) v = bl[0] + 0.5f * bl[2];
        else               v = bl[1] + 0.5f * bl[3];
        g_bn[b * 4 + tid] = fminf(fmaxf(v, 0.0f), 1.0f);
    }
}

// ---------------- stage 3: ROI max-pool, float4 loads + masked max ------------------
// 1536 blocks (s,b,c), 256 thr = 2 threads/bin (y-split). Row segments loaded as
// 16B-aligned float4 (alignment: channel/row strides are multiples of 32 floats,
// xb rounded to x4); out-of-bin lanes masked to -inf. ~3.5x fewer LDG dispatches.
__global__ void __launch_bounds__(256) k_roi(const float* __restrict__ x1p,
                                             const float* __restrict__ x2p,
                                             const float* __restrict__ x3p) {
    __shared__ float sm[128];
    const int bx = blockIdx.x;        // 1536
    const int s = bx >> 9;
    const int rem = bx & 511;
    const int b = rem >> 6, c = rem & 63;
    const int HW = (s == 0) ? 128 : (s == 1) ? 64 : 32;
    const float* xp = (s == 0) ? x1p : (s == 1) ? x2p : x3p;

    const float Sf = (float)HW;
    const int X1 = (int)floorf(g_bn[b * 4 + 0] * Sf), Y1 = (int)floorf(g_bn[b * 4 + 1] * Sf);
    const int X2 = (int)floorf(g_bn[b * 4 + 2] * Sf), Y2 = (int)floorf(g_bn[b * 4 + 3] * Sf);
    const bool valid = (X2 < HW) && (Y2 < HW) && (X2 > X1) && (Y2 > Y1);

    const int tid = threadIdx.x;
    const int bin = tid & 127, half = tid >> 7;
    float m = -3.0e38f;
    if (valid) {
        const int h = Y2 - Y1 + 1, w = X2 - X1 + 1;
        const int i = bin >> 3, j = bin & 7;
        const int lo_i = (i * h) >> 4, hi_i = ((i + 1) * h + 15) >> 4;
        const int lo_j = (j * w) >> 3, hi_j = ((j + 1) * w + 7) >> 3;
        const int mid = (lo_i + hi_i + 1) >> 1;
        const int y0 = half ? mid : lo_i;
        const int y1 = half ? hi_i : mid;
        const int ax_lo = X1 + lo_j;          // absolute column range [ax_lo, ax_hi)
        const int ax_hi = X1 + hi_j;
        const int axs = ax_lo & ~3;           // aligned start
        const float* chan = xp + (size_t)(b * 64 + c) * HW * HW;
        for (int y = y0; y < y1; y++) {
            const float* row = chan + (size_t)(Y1 + y) * HW;
            for (int xb = axs; xb < ax_hi; xb += 4) {
                float4 v = *(const float4*)(row + xb);
                float v0 = (xb     >= ax_lo)                   ? v.x : -3.0e38f;
                float v1 = (xb + 1 >= ax_lo && xb + 1 < ax_hi) ? v.y : -3.0e38f;
                float v2 = (xb + 2 >= ax_lo && xb + 2 < ax_hi) ? v.z : -3.0e38f;
                float v3 = (xb + 3 < ax_hi)                    ? v.w : -3.0e38f;
                m = fmaxf(m, fmaxf(fmaxf(v0, v1), fmaxf(v2, v3)));
            }
        }
    }
    if (half) sm[bin] = m;
    __syncthreads();
    if (!half) {
        float out = valid ? fmaxf(m, sm[bin]) : 0.f;
        g_feat[b * 24576 + (s * 64 + c) * 128 + bin] = out;
    }
}

// ---------------- stage 4: head GEMM, packed f32x2 (R8-proven) ----------------------
__global__ void __launch_bounds__(256) k_head_part(const float* __restrict__ hw) {
    __shared__ __align__(16) float fst[192 * 10];
    __shared__ __align__(16) float red[4 * 1024];
    const int bx = blockIdx.x;
    const int k = bx >> 7, ch = bx & 127;
    const int d0 = ch * 192;
    const int tid = threadIdx.x;

    if (tid < 192) {
#pragma unroll
        for (int r = 0; r < 8; r++)
            fst[tid * 10 + r] = g_feat[r * 24576 + d0 + tid];
    }
    __syncthreads();

    const int wq = tid >> 5, lane = tid & 31;
    const float4* w4 = (const float4*)hw;
    const size_t wbase = ((size_t)k * 24576 + d0 + wq * 24) * 32 + lane;
    unsigned long long acc2[4][4] = {};
#pragma unroll
    for (int dd = 0; dd < 24; dd++) {
        float4 wv = w4[wbase + (size_t)dd * 32];
        const int fi = wq * 24 + dd;
        unsigned long long fp[4];
#pragma unroll
        for (int p = 0; p < 4; p++)
            fp[p] = *(const unsigned long long*)&fst[fi * 10 + 2 * p];
        unsigned long long wp_[4];
        asm("mov.b64 %0, {%1, %1};" : "=l"(wp_[0]) : "f"(wv.x));
        asm("mov.b64 %0, {%1, %1};" : "=l"(wp_[1]) : "f"(wv.y));
        asm("mov.b64 %0, {%1, %1};" : "=l"(wp_[2]) : "f"(wv.z));
        asm("mov.b64 %0, {%1, %1};" : "=l"(wp_[3]) : "f"(wv.w));
#pragma unroll
        for (int p = 0; p < 4; p++)
#pragma unroll
            for (int j = 0; j < 4; j++)
                asm("fma.rn.f32x2 %0, %1, %2, %0;"
                    : "+l"(acc2[p][j]) : "l"(fp[p]), "l"(wp_[j]));
    }

    float acc[8][4];
#pragma unroll
    for (int p = 0; p < 4; p++)
#pragma unroll
        for (int j = 0; j < 4; j++) {
            float lo, hi;
            asm("mov.b64 {%0, %1}, %2;" : "=f"(lo), "=f"(hi) : "l"(acc2[p][j]));
            acc[2 * p][j] = lo; acc[2 * p + 1][j] = hi;
        }

    float* myred = red + (wq & 3) * 1024;
    if (wq < 4) {
#pragma unroll
        for (int r = 0; r < 8; r++)
            *(float4*)&myred[r * 128 + lane * 4] =
                make_float4(acc[r][0], acc[r][1], acc[r][2], acc[r][3]);
    }
    __syncthreads();
    if (wq >= 4) {
#pragma unroll
        for (int r = 0; r < 8; r++) {
            float4* p = (float4*)&myred[r * 128 + lane * 4];
            float4 v = *p;
            v.x += acc[r][0]; v.y += acc[r][1]; v.z += acc[r][2]; v.w += acc[r][3];
            *p = v;
        }
    }
    __syncthreads();
    float4 sv = *(const float4*)&red[tid * 4];
#pragma unroll
    for (int w = 1; w < 4; w++) {
        float4 t4 = *(const float4*)&red[w * 1024 + tid * 4];
        sv.x += t4.x; sv.y += t4.y; sv.z += t4.z; sv.w += t4.w;
    }
    const int r = tid >> 5, hcol = (tid & 31) * 4;
    *(float4*)&g_part2[(((size_t)k * 128 + ch) * 8 + r) * 128 + hcol] = sv;
}

// ---------------- stage 5: reduce + bias + relu + output heads (fused) --------------
__global__ void __launch_bounds__(512) k_head_final(
        const float* __restrict__ hb,
        const float* __restrict__ wp, const float* __restrict__ bp,
        const float* __restrict__ wa, const float* __restrict__ ba,
        const float* __restrict__ wad, const float* __restrict__ bad,
        float* __restrict__ out) {
    __shared__ float red2[512];
    __shared__ float hs[128];
    const int kb = blockIdx.x;
    const int k = kb >> 3, b = kb & 7;
    const int tid = threadIdx.x;
    const int h = tid & 127, cp = tid >> 7;

    float s = 0.f;
#pragma unroll 8
    for (int q = 0; q < 32; q++) {
        int ch = cp * 32 + q;
        s += g_part2[(((size_t)k * 128 + ch) * 8 + b) * 128 + h];
    }
    red2[tid] = s;
    __syncthreads();
    if (tid < 128) {
        float v = red2[tid] + red2[tid + 128] + red2[tid + 256] + red2[tid + 384];
        hs[tid] = fmaxf(v + hb[k * 128 + tid], 0.f);
    }
    __syncthreads();

    int O, off;
    const float *Wk, *Bk;
    if (k == 0)      { O = 38; Wk = wp; Bk = bp; off = 0; }
    else if (k == 1) { O = 25; Wk = wa; Bk = ba; off = 304; }
    else             { O = 35; Wk = wad + (k - 2) * 128 * 35; Bk = bad + (k - 2) * 35;
                       off = 504 + (k - 2) * 280; }
    const int o = tid & 127, grp = tid >> 7;
    if (o < O) {
        float acc = 0.f;
#pragma unroll 4
        for (int hh = grp * 32; hh < grp * 32 + 32; hh++)
            acc = fmaf(hs[hh], Wk[hh * O + o], acc);
        red2[grp * 128 + o] = acc;
    }
    __syncthreads();
    if (tid < O) {
        float acc = red2[tid] + red2[128 + tid] + red2[256 + tid] + red2[384 + tid];
        out[off + b * O + tid] = acc + Bk[tid];
    }
}

// ---------------- launch ----------------
extern "C" void kernel_launch(void* const* d_in, const int* in_sizes, int n_in,
                              void* d_out, int out_size) {
    (void)in_sizes; (void)n_in; (void)out_size;
    const float* x1 = (const float*)d_in[0];
    const float* x2 = (const float*)d_in[1];
    const float* x3 = (const float*)d_in[2];
    const float* w1 = (const float*)d_in[5];
    const float* b1 = (const float*)d_in[6];
    const float* w2 = (const float*)d_in[7];
    const float* b2 = (const float*)d_in[8];
    const float* w3 = (const float*)d_in[9];
    const float* b3 = (const float*)d_in[10];
    const float* hw = (const float*)d_in[11];
    const float* hb = (const float*)d_in[12];
    const float* wp = (const float*)d_in[13];
    const float* bp = (const float*)d_in[14];
    const float* wa = (const float*)d_in[15];
    const float* ba = (const float*)d_in[16];
    const float* wad = (const float*)d_in[17];
    const float* bad = (const float*)d_in[18];
    float* out = (float*)d_out;

    k_gemm1_part<<<512, 128>>>(x3, w1);
    k_reduce_a<<<64, 256>>>();
    k_box<<<8, 128>>>(b1, w2, b2, w3, b3);
    k_roi<<<1536, 256>>>(x1, x2, x3);
    k_head_part<<<896, 256>>>(hw);
    k_head_final<<<56, 512>>>(hb, wp, bp, wa, ba, wad, bad, out);
}

// round 13
// speedup vs baseline: 1.0971x; 1.0971x over previous
#include <cuda_runtime.h>
#include <math.h>

// ---------------- scratch (static device globals; no allocation) ----------------
__device__ float g_part1[512 * 800];           // gemm1 partials: [chunk][r*100+j]
__device__ float g_p1b[800 * 64];              // stage-A reduced: [o][cgroup]
__device__ float g_bn[32];                     // boxNew (8,4)
__device__ float g_feat[8 * 24576];            // pooled features (B, 3*64*128)
__device__ float g_part2[7 * 192 * 8 * 128];   // head partials: [k][ch][r][h], 192 chunks

// ---------------- stage 1: xf(8x65536) @ wr2_w1(65536x100), split-K ----------------
__global__ void __launch_bounds__(128) k_gemm1_part(const float* __restrict__ x3,
                                                    const float* __restrict__ w1) {
    __shared__ __align__(16) float xs[8 * 128];
    __shared__ float red[4 * 800];
    const int bx = blockIdx.x;
    const int k0 = bx * 128;
    const int tid = threadIdx.x;

    const float4* x4 = (const float4*)x3;
    float4* xs4 = (float4*)xs;
#pragma unroll
    for (int t = 0; t < 2; t++) {
        int idx = tid + t * 128;
        int r = idx >> 5, q = idx & 31;
        xs4[idx] = x4[r * 16384 + bx * 32 + q];
    }
    __syncthreads();

    if (tid < 100) {
        const int ks = tid / 25;
        const int j4 = tid - ks * 25;
        const float4* w4 = (const float4*)w1;
        float acc[8][4] = {};
#pragma unroll
        for (int t = 0; t < 32; t++) {
            int kk = ks + 4 * t;
            float4 wv = w4[(size_t)(k0 + kk) * 25 + j4];
#pragma unroll
            for (int r = 0; r < 8; r++) {
                float f = xs[r * 128 + kk];
                acc[r][0] = fmaf(f, wv.x, acc[r][0]);
                acc[r][1] = fmaf(f, wv.y, acc[r][1]);
                acc[r][2] = fmaf(f, wv.z, acc[r][2]);
                acc[r][3] = fmaf(f, wv.w, acc[r][3]);
            }
        }
#pragma unroll
        for (int jj = 0; jj < 4; jj++)
#pragma unroll
            for (int r = 0; r < 8; r++)
                red[ks * 800 + r * 100 + j4 * 4 + jj] = acc[r][jj];
    }
    __syncthreads();
    for (int t = tid; t < 800; t += 128) {
        float s = red[t] + red[800 + t] + red[1600 + t] + red[2400 + t];
        g_part1[(size_t)bx * 800 + t] = s;
    }
}

// ---------------- stage 1b: coalesced stage-A reduce (64 blocks x 256) --------------
__global__ void __launch_bounds__(256) k_reduce_a() {
    const int cg = blockIdx.x;
    const int tid = threadIdx.x;
    float a0 = 0.f, a1 = 0.f, a2 = 0.f, a3 = 0.f;
    const float* base = g_part1 + (size_t)cg * 8 * 800;
#pragma unroll
    for (int q = 0; q < 8; q++) {
        const float* row = base + q * 800;
        a0 += row[tid];
        a1 += row[tid + 256];
        a2 += row[tid + 512];
        if (tid < 32) a3 += row[tid + 768];
    }
    g_p1b[(size_t)tid * 64 + cg] = a0;
    g_p1b[(size_t)(tid + 256) * 64 + cg] = a1;
    g_p1b[(size_t)(tid + 512) * 64 + cg] = a2;
    if (tid < 32) g_p1b[(size_t)(tid + 768) * 64 + cg] = a3;
}

// ---------------- stage 2: stage-B reduce + MLP + box transform (8 blocks) ----------
__global__ void __launch_bounds__(128) k_box(const float* __restrict__ b1,
                                             const float* __restrict__ w2,
                                             const float* __restrict__ b2,
                                             const float* __restrict__ w3,
                                             const float* __restrict__ b3) {
    __shared__ __align__(16) float w2s[10000];
    __shared__ float t1[100], t2[104], bl[4];
    const int b = blockIdx.x;
    const int tid = threadIdx.x;

    const float4* w24 = (const float4*)w2;
    float4* w2s4 = (float4*)w2s;
    for (int t = tid; t < 2500; t += 128) w2s4[t] = w24[t];

    if (tid < 100) {
        const float4* p = (const float4*)&g_p1b[(size_t)(b * 100 + tid) * 64];
        float s = 0.f;
#pragma unroll
        for (int q = 0; q < 16; q++) {
            float4 v = p[q];
            s += v.x + v.y + v.z + v.w;
        }
        t1[tid] = s + b1[tid];
    }
    __syncthreads();

    if (tid < 100) {
        float acc = b2[tid];
#pragma unroll 4
        for (int i = 0; i < 100; i++) acc = fmaf(t1[i], w2s[i * 100 + tid], acc);
        t2[tid] = acc;
    }
    __syncthreads();
    if (tid < 4) {
        float acc = b3[tid];
#pragma unroll 4
        for (int i = 0; i < 100; i++) acc = fmaf(t2[i], w3[i * 4 + tid], acc);
        bl[tid] = acc;
    }
    __syncthreads();
    if (tid < 4) {
        float v;
        if (tid == 0)      v = bl[0] - 0.5f * bl[2];
        else if (tid == 1) v = bl[1] - 0.5f * bl[3];
        else if (tid == 2) v = bl[0] + 0.5f * bl[2];
        else               v = bl[1] + 0.5f * bl[3];
        g_bn[b * 4 + tid] = fminf(fmaxf(v, 0.0f), 1.0f);
    }
}

// ---------------- stage 3: ROI max-pool (R8 scalar 2-thread/bin), scale-split -------
// s_base=0: grid 512 (s=0). s_base=1: grid 1024 (s=1,2).
__global__ void __launch_bounds__(256) k_roi(const float* __restrict__ x1p,
                                             const float* __restrict__ x2p,
                                             const float* __restrict__ x3p,
                                             int s_base) {
    __shared__ float sm[128];
    const int s = s_base + (blockIdx.x >> 9);
    const int rem = blockIdx.x & 511;
    const int b = rem >> 6, c = rem & 63;
    const int HW = (s == 0) ? 128 : (s == 1) ? 64 : 32;
    const float* xp = (s == 0) ? x1p : (s == 1) ? x2p : x3p;

    const float Sf = (float)HW;
    const int X1 = (int)floorf(g_bn[b * 4 + 0] * Sf), Y1 = (int)floorf(g_bn[b * 4 + 1] * Sf);
    const int X2 = (int)floorf(g_bn[b * 4 + 2] * Sf), Y2 = (int)floorf(g_bn[b * 4 + 3] * Sf);
    const bool valid = (X2 < HW) && (Y2 < HW) && (X2 > X1) && (Y2 > Y1);

    const int tid = threadIdx.x;
    const int bin = tid & 127, half = tid >> 7;
    float m = -3.0e38f;
    if (valid) {
        const int h = Y2 - Y1 + 1, w = X2 - X1 + 1;
        const int i = bin >> 3, j = bin & 7;
        const int lo_i = (i * h) >> 4, hi_i = ((i + 1) * h + 15) >> 4;
        const int lo_j = (j * w) >> 3, hi_j = ((j + 1) * w + 7) >> 3;
        const int mid = (lo_i + hi_i + 1) >> 1;
        const int y0 = half ? mid : lo_i;
        const int y1 = half ? hi_i : mid;
        const float* base = xp + ((size_t)(b * 64 + c) * HW + Y1) * HW + X1;
        for (int y = y0; y < y1; y++) {
            const float* row = base + y * HW;
            for (int xx = lo_j; xx < hi_j; xx++) m = fmaxf(m, row[xx]);
        }
    }
    if (half) sm[bin] = m;
    __syncthreads();
    if (!half) {
        float out = valid ? fmaxf(m, sm[bin]) : 0.f;
        g_feat[b * 24576 + (s * 64 + c) * 128 + bin] = out;
    }
}

// ---------------- stage 4: head GEMM, 128-d chunks, f32x2 (chunk-split by scale) -----
// grid = 7 * nch. ch in [ch_base, ch_base+nch). Warp owns 16 d, thread 4 h (LDG.128).
__global__ void __launch_bounds__(256) k_head_part(const float* __restrict__ hw,
                                                   int ch_base, int nch) {
    __shared__ __align__(16) float fst[128 * 10];
    __shared__ __align__(16) float red[4 * 1024];
    const int bx = blockIdx.x;
    const int k = bx / nch, ch = ch_base + (bx - k * nch);
    const int d0 = ch * 128;
    const int tid = threadIdx.x;

    if (tid < 128) {
#pragma unroll
        for (int r = 0; r < 8; r++)
            fst[tid * 10 + r] = g_feat[r * 24576 + d0 + tid];
    }
    __syncthreads();

    const int wq = tid >> 5, lane = tid & 31;
    const float4* w4 = (const float4*)hw;
    const size_t wbase = ((size_t)k * 24576 + d0 + wq * 16) * 32 + lane;
    unsigned long long acc2[4][4] = {};
#pragma unroll
    for (int dd = 0; dd < 16; dd++) {
        float4 wv = w4[wbase + (size_t)dd * 32];
        const int fi = wq * 16 + dd;
        unsigned long long fp[4];
#pragma unroll
        for (int p = 0; p < 4; p++)
            fp[p] = *(const unsigned long long*)&fst[fi * 10 + 2 * p];
        unsigned long long wp_[4];
        asm("mov.b64 %0, {%1, %1};" : "=l"(wp_[0]) : "f"(wv.x));
        asm("mov.b64 %0, {%1, %1};" : "=l"(wp_[1]) : "f"(wv.y));
        asm("mov.b64 %0, {%1, %1};" : "=l"(wp_[2]) : "f"(wv.z));
        asm("mov.b64 %0, {%1, %1};" : "=l"(wp_[3]) : "f"(wv.w));
#pragma unroll
        for (int p = 0; p < 4; p++)
#pragma unroll
            for (int j = 0; j < 4; j++)
                asm("fma.rn.f32x2 %0, %1, %2, %0;"
                    : "+l"(acc2[p][j]) : "l"(fp[p]), "l"(wp_[j]));
    }

    float acc[8][4];
#pragma unroll
    for (int p = 0; p < 4; p++)
#pragma unroll
        for (int j = 0; j < 4; j++) {
            float lo, hi;
            asm("mov.b64 {%0, %1}, %2;" : "=f"(lo), "=f"(hi) : "l"(acc2[p][j]));
            acc[2 * p][j] = lo; acc[2 * p + 1][j] = hi;
        }

    float* myred = red + (wq & 3) * 1024;
    if (wq < 4) {
#pragma unroll
        for (int r = 0; r < 8; r++)
            *(float4*)&myred[r * 128 + lane * 4] =
                make_float4(acc[r][0], acc[r][1], acc[r][2], acc[r][3]);
    }
    __syncthreads();
    if (wq >= 4) {
#pragma unroll
        for (int r = 0; r < 8; r++) {
            float4* p = (float4*)&myred[r * 128 + lane * 4];
            float4 v = *p;
            v.x += acc[r][0]; v.y += acc[r][1]; v.z += acc[r][2]; v.w += acc[r][3];
            *p = v;
        }
    }
    __syncthreads();
    float4 sv = *(const float4*)&red[tid * 4];
#pragma unroll
    for (int w = 1; w < 4; w++) {
        float4 t4 = *(const float4*)&red[w * 1024 + tid * 4];
        sv.x += t4.x; sv.y += t4.y; sv.z += t4.z; sv.w += t4.w;
    }
    const int r = tid >> 5, hcol = (tid & 31) * 4;
    *(float4*)&g_part2[(((size_t)k * 192 + ch) * 8 + r) * 128 + hcol] = sv;
}

// ---------------- stage 5: reduce(192 chunks) + bias + relu + output heads ----------
__global__ void __launch_bounds__(512) k_head_final(
        const float* __restrict__ hb,
        const float* __restrict__ wp, const float* __restrict__ bp,
        const float* __restrict__ wa, const float* __restrict__ ba,
        const float* __restrict__ wad, const float* __restrict__ bad,
        float* __restrict__ out) {
    __shared__ float red2[512];
    __shared__ float hs[128];
    const int kb = blockIdx.x;
    const int k = kb >> 3, b = kb & 7;
    const int tid = threadIdx.x;
    const int h = tid & 127, cp = tid >> 7;

    float s = 0.f;
#pragma unroll 8
    for (int q = 0; q < 48; q++) {
        int ch = cp * 48 + q;
        s += g_part2[(((size_t)k * 192 + ch) * 8 + b) * 128 + h];
    }
    red2[tid] = s;
    __syncthreads();
    if (tid < 128) {
        float v = red2[tid] + red2[tid + 128] + red2[tid + 256] + red2[tid + 384];
        hs[tid] = fmaxf(v + hb[k * 128 + tid], 0.f);
    }
    __syncthreads();

    int O, off;
    const float *Wk, *Bk;
    if (k == 0)      { O = 38; Wk = wp; Bk = bp; off = 0; }
    else if (k == 1) { O = 25; Wk = wa; Bk = ba; off = 304; }
    else             { O = 35; Wk = wad + (k - 2) * 128 * 35; Bk = bad + (k - 2) * 35;
                       off = 504 + (k - 2) * 280; }
    const int o = tid & 127, grp = tid >> 7;
    if (o < O) {
        float acc = 0.f;
#pragma unroll 4
        for (int hh = grp * 32; hh < grp * 32 + 32; hh++)
            acc = fmaf(hs[hh], Wk[hh * O + o], acc);
        red2[grp * 128 + o] = acc;
    }
    __syncthreads();
    if (tid < O) {
        float acc = red2[tid] + red2[128 + tid] + red2[256 + tid] + red2[384 + tid];
        out[off + b * O + tid] = acc + Bk[tid];
    }
}

// ---------------- launch: fork-join two-branch pipeline ----------------
extern "C" void kernel_launch(void* const* d_in, const int* in_sizes, int n_in,
                              void* d_out, int out_size) {
    (void)in_sizes; (void)n_in; (void)out_size;
    const float* x1 = (const float*)d_in[0];
    const float* x2 = (const float*)d_in[1];
    const float* x3 = (const float*)d_in[2];
    const float* w1 = (const float*)d_in[5];
    const float* b1 = (const float*)d_in[6];
    const float* w2 = (const float*)d_in[7];
    const float* b2 = (const float*)d_in[8];
    const float* w3 = (const float*)d_in[9];
    const float* b3 = (const float*)d_in[10];
    const float* hw = (const float*)d_in[11];
    const float* hb = (const float*)d_in[12];
    const float* wp = (const float*)d_in[13];
    const float* bp = (const float*)d_in[14];
    const float* wa = (const float*)d_in[15];
    const float* ba = (const float*)d_in[16];
    const float* wad = (const float*)d_in[17];
    const float* bad = (const float*)d_in[18];
    float* out = (float*)d_out;

    // one-time side-stream/event resources (host objects, no device memory)
    static cudaStream_t sB = nullptr;
    static cudaEvent_t evFork = nullptr, evB = nullptr;
    if (sB == nullptr) {
        cudaStreamCreateWithFlags(&sB, cudaStreamNonBlocking);
        cudaEventCreateWithFlags(&evFork, cudaEventDisableTiming);
        cudaEventCreateWithFlags(&evB, cudaEventDisableTiming);
    }

    k_gemm1_part<<<512, 128>>>(x3, w1);
    k_reduce_a<<<64, 256>>>();
    k_box<<<8, 128>>>(b1, w2, b2, w3, b3);

    // fork: branch B (s=1,2) on side stream
    cudaEventRecord(evFork, 0);
    cudaStreamWaitEvent(sB, evFork, 0);
    k_roi<<<1024, 256, 0, sB>>>(x1, x2, x3, 1);          // s=1,2 (x2,x3)
    k_head_part<<<896, 256, 0, sB>>>(hw, 64, 128);        // ch 64..191 (59MB weights)
    cudaEventRecord(evB, sB);

    // branch A (s=0) on main stream, concurrent with B
    k_roi<<<512, 256>>>(x1, x2, x3, 0);                   // s=0 (x1, 16MB)
    k_head_part<<<448, 256>>>(hw, 0, 64);                 // ch 0..63 (29MB weights)

    // join, then final
    cudaStreamWaitEvent(0, evB, 0);
    k_head_final<<<56, 512>>>(hb, wp, bp, wa, ba, wad, bad, out);
}

// round 14
// speedup vs baseline: 1.1284x; 1.0285x over previous
#include <cuda_runtime.h>
#include <math.h>

// ---------------- scratch (static device globals; no allocation) ----------------
__device__ float g_part1[512 * 800];           // gemm1 partials: [chunk][r*100+j]
__device__ float g_p1b[800 * 64];              // stage-A reduced: [o][cgroup]
__device__ float g_bn[32];                     // boxNew (8,4)
__device__ float g_feat[8 * 24576];            // pooled features (B, 3*64*128)
__device__ float g_part2[7 * 96 * 8 * 128];    // head partials: [k][ch][r][h], 96 chunks

// ---------------- stage 1: xf(8x65536) @ wr2_w1(65536x100), split-K ----------------
__global__ void __launch_bounds__(128) k_gemm1_part(const float* __restrict__ x3,
                                                    const float* __restrict__ w1) {
    __shared__ __align__(16) float xs[8 * 128];
    __shared__ float red[4 * 800];
    const int bx = blockIdx.x;
    const int k0 = bx * 128;
    const int tid = threadIdx.x;

    const float4* x4 = (const float4*)x3;
    float4* xs4 = (float4*)xs;
#pragma unroll
    for (int t = 0; t < 2; t++) {
        int idx = tid + t * 128;
        int r = idx >> 5, q = idx & 31;
        xs4[idx] = x4[r * 16384 + bx * 32 + q];
    }
    __syncthreads();

    if (tid < 100) {
        const int ks = tid / 25;
        const int j4 = tid - ks * 25;
        const float4* w4 = (const float4*)w1;
        float acc[8][4] = {};
#pragma unroll
        for (int t = 0; t < 32; t++) {
            int kk = ks + 4 * t;
            float4 wv = w4[(size_t)(k0 + kk) * 25 + j4];
#pragma unroll
            for (int r = 0; r < 8; r++) {
                float f = xs[r * 128 + kk];
                acc[r][0] = fmaf(f, wv.x, acc[r][0]);
                acc[r][1] = fmaf(f, wv.y, acc[r][1]);
                acc[r][2] = fmaf(f, wv.z, acc[r][2]);
                acc[r][3] = fmaf(f, wv.w, acc[r][3]);
            }
        }
#pragma unroll
        for (int jj = 0; jj < 4; jj++)
#pragma unroll
            for (int r = 0; r < 8; r++)
                red[ks * 800 + r * 100 + j4 * 4 + jj] = acc[r][jj];
    }
    __syncthreads();
    for (int t = tid; t < 800; t += 128) {
        float s = red[t] + red[800 + t] + red[1600 + t] + red[2400 + t];
        g_part1[(size_t)bx * 800 + t] = s;
    }
}

// ---------------- stage 1b: coalesced stage-A reduce (64 blocks x 256) --------------
__global__ void __launch_bounds__(256) k_reduce_a() {
    const int cg = blockIdx.x;
    const int tid = threadIdx.x;
    float a0 = 0.f, a1 = 0.f, a2 = 0.f, a3 = 0.f;
    const float* base = g_part1 + (size_t)cg * 8 * 800;
#pragma unroll
    for (int q = 0; q < 8; q++) {
        const float* row = base + q * 800;
        a0 += row[tid];
        a1 += row[tid + 256];
        a2 += row[tid + 512];
        if (tid < 32) a3 += row[tid + 768];
    }
    g_p1b[(size_t)tid * 64 + cg] = a0;
    g_p1b[(size_t)(tid + 256) * 64 + cg] = a1;
    g_p1b[(size_t)(tid + 512) * 64 + cg] = a2;
    if (tid < 32) g_p1b[(size_t)(tid + 768) * 64 + cg] = a3;
}

// ---------------- stage 2: stage-B reduce + MLP + box transform (8 blocks) ----------
__global__ void __launch_bounds__(128) k_box(const float* __restrict__ b1,
                                             const float* __restrict__ w2,
                                             const float* __restrict__ b2,
                                             const float* __restrict__ w3,
                                             const float* __restrict__ b3) {
    __shared__ __align__(16) float w2s[10000];
    __shared__ float t1[100], t2[104], bl[4];
    const int b = blockIdx.x;
    const int tid = threadIdx.x;

    const float4* w24 = (const float4*)w2;
    float4* w2s4 = (float4*)w2s;
    for (int t = tid; t < 2500; t += 128) w2s4[t] = w24[t];

    if (tid < 100) {
        const float4* p = (const float4*)&g_p1b[(size_t)(b * 100 + tid) * 64];
        float s = 0.f;
#pragma unroll
        for (int q = 0; q < 16; q++) {
            float4 v = p[q];
            s += v.x + v.y + v.z + v.w;
        }
        t1[tid] = s + b1[tid];
    }
    __syncthreads();

    if (tid < 100) {
        float acc = b2[tid];
#pragma unroll 4
        for (int i = 0; i < 100; i++) acc = fmaf(t1[i], w2s[i * 100 + tid], acc);
        t2[tid] = acc;
    }
    __syncthreads();
    if (tid < 4) {
        float acc = b3[tid];
#pragma unroll 4
        for (int i = 0; i < 100; i++) acc = fmaf(t2[i], w3[i * 4 + tid], acc);
        bl[tid] = acc;
    }
    __syncthreads();
    if (tid < 4) {
        float v;
        if (tid == 0)      v = bl[0] - 0.5f * bl[2];
        else if (tid == 1) v = bl[1] - 0.5f * bl[3];
        else if (tid == 2) v = bl[0] + 0.5f * bl[2];
        else               v = bl[1] + 0.5f * bl[3];
        g_bn[b * 4 + tid] = fminf(fmaxf(v, 0.0f), 1.0f);
    }
}

// ---------------- stage 3: ROI max-pool (R8 scalar 2-thread/bin), scale-split -------
__global__ void __launch_bounds__(256) k_roi(const float* __restrict__ x1p,
                                             const float* __restrict__ x2p,
                                             const float* __restrict__ x3p,
                                             int s_base) {
    __shared__ float sm[128];
    const int s = s_base + (blockIdx.x >> 9);
    const int rem = blockIdx.x & 511;
    const int b = rem >> 6, c = rem & 63;
    const int HW = (s == 0) ? 128 : (s == 1) ? 64 : 32;
    const float* xp = (s == 0) ? x1p : (s == 1) ? x2p : x3p;

    const float Sf = (float)HW;
    const int X1 = (int)floorf(g_bn[b * 4 + 0] * Sf), Y1 = (int)floorf(g_bn[b * 4 + 1] * Sf);
    const int X2 = (int)floorf(g_bn[b * 4 + 2] * Sf), Y2 = (int)floorf(g_bn[b * 4 + 3] * Sf);
    const bool valid = (X2 < HW) && (Y2 < HW) && (X2 > X1) && (Y2 > Y1);

    const int tid = threadIdx.x;
    const int bin = tid & 127, half = tid >> 7;
    float m = -3.0e38f;
    if (valid) {
        const int h = Y2 - Y1 + 1, w = X2 - X1 + 1;
        const int i = bin >> 3, j = bin & 7;
        const int lo_i = (i * h) >> 4, hi_i = ((i + 1) * h + 15) >> 4;
        const int lo_j = (j * w) >> 3, hi_j = ((j + 1) * w + 7) >> 3;
        const int mid = (lo_i + hi_i + 1) >> 1;
        const int y0 = half ? mid : lo_i;
        const int y1 = half ? hi_i : mid;
        const float* base = xp + ((size_t)(b * 64 + c) * HW + Y1) * HW + X1;
        for (int y = y0; y < y1; y++) {
            const float* row = base + y * HW;
            for (int xx = lo_j; xx < hi_j; xx++) m = fmaxf(m, row[xx]);
        }
    }
    if (half) sm[bin] = m;
    __syncthreads();
    if (!half) {
        float out = valid ? fmaxf(m, sm[bin]) : 0.f;
        g_feat[b * 24576 + (s * 64 + c) * 128 + bin] = out;
    }
}

// ---------------- stage 4: head GEMM, 256-d chunks, f32x2 ---------------------------
// 96 chunks of 256 d; scale boundary d=8192 = chunk 32 (exact). Warp owns 32 d,
// thread owns 4 h via LDG.128. Two-phase in-place cross-warp reduce.
__global__ void __launch_bounds__(256) k_head_part(const float* __restrict__ hw,
                                                   int ch_base, int nch) {
    __shared__ __align__(16) float fst[256 * 10];
    __shared__ __align__(16) float red[4 * 1024];
    const int bx = blockIdx.x;
    const int k = bx / nch, ch = ch_base + (bx - k * nch);
    const int d0 = ch * 256;
    const int tid = threadIdx.x;

#pragma unroll
    for (int r = 0; r < 8; r++)
        fst[tid * 10 + r] = g_feat[r * 24576 + d0 + tid];
    __syncthreads();

    const int wq = tid >> 5, lane = tid & 31;
    const float4* w4 = (const float4*)hw;
    const size_t wbase = ((size_t)k * 24576 + d0 + wq * 32) * 32 + lane;
    unsigned long long acc2[4][4] = {};
#pragma unroll 8
    for (int dd = 0; dd < 32; dd++) {
        float4 wv = w4[wbase + (size_t)dd * 32];
        const int fi = wq * 32 + dd;
        unsigned long long fp[4];
#pragma unroll
        for (int p = 0; p < 4; p++)
            fp[p] = *(const unsigned long long*)&fst[fi * 10 + 2 * p];
        unsigned long long wp_[4];
        asm("mov.b64 %0, {%1, %1};" : "=l"(wp_[0]) : "f"(wv.x));
        asm("mov.b64 %0, {%1, %1};" : "=l"(wp_[1]) : "f"(wv.y));
        asm("mov.b64 %0, {%1, %1};" : "=l"(wp_[2]) : "f"(wv.z));
        asm("mov.b64 %0, {%1, %1};" : "=l"(wp_[3]) : "f"(wv.w));
#pragma unroll
        for (int p = 0; p < 4; p++)
#pragma unroll
            for (int j = 0; j < 4; j++)
                asm("fma.rn.f32x2 %0, %1, %2, %0;"
                    : "+l"(acc2[p][j]) : "l"(fp[p]), "l"(wp_[j]));
    }

    float acc[8][4];
#pragma unroll
    for (int p = 0; p < 4; p++)
#pragma unroll
        for (int j = 0; j < 4; j++) {
            float lo, hi;
            asm("mov.b64 {%0, %1}, %2;" : "=f"(lo), "=f"(hi) : "l"(acc2[p][j]));
            acc[2 * p][j] = lo; acc[2 * p + 1][j] = hi;
        }

    float* myred = red + (wq & 3) * 1024;
    if (wq < 4) {
#pragma unroll
        for (int r = 0; r < 8; r++)
            *(float4*)&myred[r * 128 + lane * 4] =
                make_float4(acc[r][0], acc[r][1], acc[r][2], acc[r][3]);
    }
    __syncthreads();
    if (wq >= 4) {
#pragma unroll
        for (int r = 0; r < 8; r++) {
            float4* p = (float4*)&myred[r * 128 + lane * 4];
            float4 v = *p;
            v.x += acc[r][0]; v.y += acc[r][1]; v.z += acc[r][2]; v.w += acc[r][3];
            *p = v;
        }
    }
    __syncthreads();
    float4 sv = *(const float4*)&red[tid * 4];
#pragma unroll
    for (int w = 1; w < 4; w++) {
        float4 t4 = *(const float4*)&red[w * 1024 + tid * 4];
        sv.x += t4.x; sv.y += t4.y; sv.z += t4.z; sv.w += t4.w;
    }
    const int r = tid >> 5, hcol = (tid & 31) * 4;
    *(float4*)&g_part2[(((size_t)k * 96 + ch) * 8 + r) * 128 + hcol] = sv;
}

// ---------------- stage 5: reduce(96 chunks) + bias + relu + output heads -----------
__global__ void __launch_bounds__(512) k_head_final(
        const float* __restrict__ hb,
        const float* __restrict__ wp, const float* __restrict__ bp,
        const float* __restrict__ wa, const float* __restrict__ ba,
        const float* __restrict__ wad, const float* __restrict__ bad,
        float* __restrict__ out) {
    __shared__ float red2[512];
    __shared__ float hs[128];
    const int kb = blockIdx.x;
    const int k = kb >> 3, b = kb & 7;
    const int tid = threadIdx.x;
    const int h = tid & 127, cp = tid >> 7;

    float s = 0.f;
#pragma unroll 8
    for (int q = 0; q < 24; q++) {
        int ch = cp * 24 + q;
        s += g_part2[(((size_t)k * 96 + ch) * 8 + b) * 128 + h];
    }
    red2[tid] = s;
    __syncthreads();
    if (tid < 128) {
        float v = red2[tid] + red2[tid + 128] + red2[tid + 256] + red2[tid + 384];
        hs[tid] = fmaxf(v + hb[k * 128 + tid], 0.f);
    }
    __syncthreads();

    int O, off;
    const float *Wk, *Bk;
    if (k == 0)      { O = 38; Wk = wp; Bk = bp; off = 0; }
    else if (k == 1) { O = 25; Wk = wa; Bk = ba; off = 304; }
    else             { O = 35; Wk = wad + (k - 2) * 128 * 35; Bk = bad + (k - 2) * 35;
                       off = 504 + (k - 2) * 280; }
    const int o = tid & 127, grp = tid >> 7;
    if (o < O) {
        float acc = 0.f;
#pragma unroll 4
        for (int hh = grp * 32; hh < grp * 32 + 32; hh++)
            acc = fmaf(hs[hh], Wk[hh * O + o], acc);
        red2[grp * 128 + o] = acc;
    }
    __syncthreads();
    if (tid < O) {
        float acc = red2[tid] + red2[128 + tid] + red2[256 + tid] + red2[384 + tid];
        out[off + b * O + tid] = acc + Bk[tid];
    }
}

// ---------------- launch: fork-join two-branch pipeline ----------------
extern "C" void kernel_launch(void* const* d_in, const int* in_sizes, int n_in,
                              void* d_out, int out_size) {
    (void)in_sizes; (void)n_in; (void)out_size;
    const float* x1 = (const float*)d_in[0];
    const float* x2 = (const float*)d_in[1];
    const float* x3 = (const float*)d_in[2];
    const float* w1 = (const float*)d_in[5];
    const float* b1 = (const float*)d_in[6];
    const float* w2 = (const float*)d_in[7];
    const float* b2 = (const float*)d_in[8];
    const float* w3 = (const float*)d_in[9];
    const float* b3 = (const float*)d_in[10];
    const float* hw = (const float*)d_in[11];
    const float* hb = (const float*)d_in[12];
    const float* wp = (const float*)d_in[13];
    const float* bp = (const float*)d_in[14];
    const float* wa = (const float*)d_in[15];
    const float* ba = (const float*)d_in[16];
    const float* wad = (const float*)d_in[17];
    const float* bad = (const float*)d_in[18];
    float* out = (float*)d_out;

    static cudaStream_t sB = nullptr;
    static cudaEvent_t evFork = nullptr, evB = nullptr;
    if (sB == nullptr) {
        cudaStreamCreateWithFlags(&sB, cudaStreamNonBlocking);
        cudaEventCreateWithFlags(&evFork, cudaEventDisableTiming);
        cudaEventCreateWithFlags(&evB, cudaEventDisableTiming);
    }

    k_gemm1_part<<<512, 128>>>(x3, w1);
    k_reduce_a<<<64, 256>>>();
    k_box<<<8, 128>>>(b1, w2, b2, w3, b3);

    // fork: branch B (s=1,2 roi -> head chunks 32..95) on side stream
    cudaEventRecord(evFork, 0);
    cudaStreamWaitEvent(sB, evFork, 0);
    k_roi<<<1024, 256, 0, sB>>>(x1, x2, x3, 1);
    k_head_part<<<448, 256, 0, sB>>>(hw, 32, 64);
    cudaEventRecord(evB, sB);

    // branch A (s=0 roi -> head chunks 0..31) on main stream
    k_roi<<<512, 256>>>(x1, x2, x3, 0);
    k_head_part<<<224, 256>>>(hw, 0, 32);

    cudaStreamWaitEvent(0, evB, 0);
    k_head_final<<<56, 512>>>(hb, wp, bp, wa, ba, wad, bad, out);
}